// round 5
// baseline (speedup 1.0000x reference)
#include <cuda_runtime.h>

#define HWC   65536   // H*W
#define QT    16384   // HWC/4 float4 per channel
#define WDIM  256
#define NKPT  68
#define OFF_SCALE 6.0f
#define BLKX  8       // blocks per batch
#define TPB   256
#define ITERS 8       // QT / BLKX / TPB

// ---------------------------------------------------------------------------
// 3x3 inverse via adjugate (fast division: polar Newton is self-correcting)
// ---------------------------------------------------------------------------
__device__ __forceinline__ void inv3(const float M[9], float Inv[9]) {
    float a = M[0], b = M[1], c = M[2];
    float d = M[3], e = M[4], f = M[5];
    float g = M[6], h = M[7], i = M[8];
    float c0 = e * i - f * h;
    float c3 = f * g - d * i;
    float c6 = d * h - e * g;
    float det = a * c0 + b * c3 + c * c6;
    float inv_det = __fdividef(1.0f, det);
    Inv[0] = c0 * inv_det;
    Inv[1] = (c * h - b * i) * inv_det;
    Inv[2] = (b * f - c * e) * inv_det;
    Inv[3] = c3 * inv_det;
    Inv[4] = (a * i - c * g) * inv_det;
    Inv[5] = (c * d - a * f) * inv_det;
    Inv[6] = c6 * inv_det;
    Inv[7] = (b * g - a * h) * inv_det;
    Inv[8] = (a * e - b * d) * inv_det;
}

__device__ __forceinline__ float warpSum(float v) {
    #pragma unroll
    for (int o = 16; o > 0; o >>= 1) v += __shfl_xor_sync(0xffffffffu, v, o);
    return v;
}

// ---------------------------------------------------------------------------
// Warp-level prep (warp 0 of each block, redundant per block).
// Writes R (scaled) and T into s_RT[12].
// ---------------------------------------------------------------------------
__device__ void prep_warp(const float* __restrict__ Off,
                          const float* __restrict__ Pos,
                          const float* __restrict__ mean,
                          const int*   __restrict__ uv,
                          int b, int lane, float* s_RT) {
    // detect int32 vs int64 uv_kpt (values in [0,256))
    int odd = 0;
    for (int i = lane; i < NKPT; i += 32) odd |= uv[2 * i + 1];
    const bool is32 = __ballot_sync(0xffffffffu, odd != 0) != 0u;

    const float* ob = Off + (size_t)b * 3 * HWC;
    const float* pb = Pos + (size_t)b * 3 * HWC;
    float sv[3][3], dv[3][3];
    bool  valid[3];
    #pragma unroll
    for (int s = 0; s < 3; s++) {
        const int k = lane + 32 * s;
        valid[s] = (k < NKPT);
        int u = 0, v = 0;
        if (valid[s]) {
            if (is32) { u = uv[2 * k]; v = uv[2 * k + 1]; }
            else      { u = uv[4 * k]; v = uv[4 * k + 2]; }
        }
        const int p = u * WDIM + v;
        #pragma unroll
        for (int c = 0; c < 3; c++) {
            sv[s][c] = valid[s] ? fmaf(__ldg(&ob[c * HWC + p]), OFF_SCALE, __ldg(&mean[c * HWC + p])) : 0.f;
            dv[s][c] = valid[s] ? __ldg(&pb[c * HWC + p]) : 0.f;
        }
    }

    // keypoint 33 = slot 1, lane 1
    float cs[3], cd[3];
    #pragma unroll
    for (int c = 0; c < 3; c++) {
        cs[c] = __shfl_sync(0xffffffffu, sv[1][c], 1);
        cd[c] = __shfl_sync(0xffffffffu, dv[1][c], 1);
    }

    float n1 = 0.f, n2 = 0.f;
    float ms[3] = {0.f, 0.f, 0.f}, md[3] = {0.f, 0.f, 0.f};
    float SDl[9] = {0.f};
    #pragma unroll
    for (int s = 0; s < 3; s++) {
        if (valid[s]) {
            float dx = sv[s][0] - cs[0], dy = sv[s][1] - cs[1], dz = sv[s][2] - cs[2];
            n1 += sqrtf(dx * dx + dy * dy + dz * dz);
            dx = dv[s][0] - cd[0]; dy = dv[s][1] - cd[1]; dz = dv[s][2] - cd[2];
            n2 += sqrtf(dx * dx + dy * dy + dz * dz);
            #pragma unroll
            for (int c = 0; c < 3; c++) { ms[c] += sv[s][c]; md[c] += dv[s][c]; }
            #pragma unroll
            for (int i = 0; i < 3; i++)
                #pragma unroll
                for (int j = 0; j < 3; j++)
                    SDl[i * 3 + j] += sv[s][i] * dv[s][j];
        }
    }

    const float sd1 = warpSum(n1);
    const float sd2 = warpSum(n2);
    float ssum[3], dsum[3], SD[9];
    #pragma unroll
    for (int c = 0; c < 3; c++) ssum[c] = warpSum(ms[c]);
    #pragma unroll
    for (int c = 0; c < 3; c++) dsum[c] = warpSum(md[c]);
    #pragma unroll
    for (int k = 0; k < 9; k++) SD[k] = warpSum(SDl[k]);

    if (lane == 0) {
        const float ratio = __fdividef(sd2, sd1);
        const float invn  = 1.0f / (float)NKPT;
        // X = H^T,  H[i][j] = ratio * (SD[i][j] - ssum[i]*dsum[j]/n)
        float X[9];
        #pragma unroll
        for (int i = 0; i < 3; i++)
            #pragma unroll
            for (int j = 0; j < 3; j++)
                X[j * 3 + i] = ratio * (SD[i * 3 + j] - ssum[i] * dsum[j] * invn);

        // Scaled Newton polar iteration -> orthogonal factor V U^T
        #pragma unroll 1
        for (int it = 0; it < 9; it++) {
            float Xi[9];
            inv3(X, Xi);
            float nx = 0.f, ni = 0.f;
            #pragma unroll
            for (int k = 0; k < 9; k++) { nx += X[k] * X[k]; ni += Xi[k] * Xi[k]; }
            float z  = sqrtf(sqrtf(__fdividef(ni, nx)));
            float zh = 0.5f * z;
            float zi = __fdividef(0.5f, z);
            float Y[9];
            #pragma unroll
            for (int i = 0; i < 3; i++)
                #pragma unroll
                for (int j = 0; j < 3; j++)
                    Y[i * 3 + j] = zh * X[i * 3 + j] + zi * Xi[j * 3 + i];
            #pragma unroll
            for (int k = 0; k < 9; k++) X[k] = Y[k];
        }

        float Am[3], Bm[3];
        #pragma unroll
        for (int c = 0; c < 3; c++) {
            Am[c] = ratio * ssum[c] * invn;
            Bm[c] = dsum[c] * invn;
        }
        #pragma unroll
        for (int k = 0; k < 9; k++) s_RT[k] = ratio * X[k];
        #pragma unroll
        for (int j = 0; j < 3; j++)
            s_RT[9 + j] = Bm[j] -
                (Am[0] * X[j * 3 + 0] + Am[1] * X[j * 3 + 1] + Am[2] * X[j * 3 + 2]);
    }
}

// ---------------------------------------------------------------------------
// Fused kernel: per-block redundant prep + streaming transform.
// grid = (BLKX, nb), block = 256.  Each block: 2048 float4-triples, 8/thread.
// out[b,j,p] = sum_i Rs[j,i]*(Off[b,i,p]*6+mean[i,p]) + T[j]
// ---------------------------------------------------------------------------
__global__ void __launch_bounds__(TPB, 6) fused_kernel(
        const float* __restrict__ Off,
        const float* __restrict__ Pos,
        const float* __restrict__ mean,
        const int*   __restrict__ uv,
        float* __restrict__ out) {
    __shared__ float s_RT[12];

    const int b   = blockIdx.y;
    const int tid = threadIdx.x;
    const int Q   = QT;

    const float4* o  = (const float4*)(Off + (size_t)b * 3 * HWC);
    const float4* m  = (const float4*)mean;
    float4*       ob = (float4*)(out + (size_t)b * 3 * HWC);

    int p = blockIdx.x * (QT / BLKX) + tid;

    // Issue first streaming iteration's loads BEFORE prep so DRAM fetch
    // overlaps the Newton chain.
    float4 a0 = o[p], a1 = o[p + Q], a2 = o[p + 2 * Q];
    float4 m0 = m[p], m1 = m[p + Q], m2 = m[p + 2 * Q];

    if (tid < 32)
        prep_warp(Off, Pos, mean, uv, b, tid, s_RT);
    __syncthreads();

    const float r00 = s_RT[0], r01 = s_RT[1], r02 = s_RT[2];
    const float r10 = s_RT[3], r11 = s_RT[4], r12 = s_RT[5];
    const float r20 = s_RT[6], r21 = s_RT[7], r22 = s_RT[8];
    const float t0  = s_RT[9], t1  = s_RT[10], t2 = s_RT[11];

    #pragma unroll 1
    for (int it = 0; ; ) {
        float4 y0, y1, y2;
#define COMP(f)                                                         \
        {                                                               \
            float c0 = fmaf(a0.f, OFF_SCALE, m0.f);                     \
            float c1 = fmaf(a1.f, OFF_SCALE, m1.f);                     \
            float c2 = fmaf(a2.f, OFF_SCALE, m2.f);                     \
            y0.f = fmaf(r00, c0, fmaf(r01, c1, fmaf(r02, c2, t0)));     \
            y1.f = fmaf(r10, c0, fmaf(r11, c1, fmaf(r12, c2, t1)));     \
            y2.f = fmaf(r20, c0, fmaf(r21, c1, fmaf(r22, c2, t2)));     \
        }
        COMP(x) COMP(y) COMP(z) COMP(w)
#undef COMP
        ob[p]         = y0;
        ob[p + Q]     = y1;
        ob[p + 2 * Q] = y2;

        if (++it == ITERS) break;
        p += TPB;
        a0 = o[p]; a1 = o[p + Q]; a2 = o[p + 2 * Q];
        m0 = m[p]; m1 = m[p + Q]; m2 = m[p + 2 * Q];
    }
}

extern "C" void kernel_launch(void* const* d_in, const int* in_sizes, int n_in,
                              void* d_out, int out_size) {
    const float* Off  = (const float*)d_in[0];
    const float* Pos  = (const float*)d_in[1];
    const float* mean = (const float*)d_in[2];
    const int*   uv   = (const int*)d_in[3];

    int nb = in_sizes[0] / (3 * HWC);

    dim3 grid(BLKX, nb);
    fused_kernel<<<grid, TPB>>>(Off, Pos, mean, uv, (float*)d_out);
}